// round 16
// baseline (speedup 1.0000x reference)
#include <cuda_runtime.h>
#include <cuda_fp16.h>
#include <cstdint>

// Problem constants
#define BB 4
#define TT 2048
#define DD 1024
#define HH 16
#define HDIM 64
#define MROWS (BB * TT)            // 8192
#define QKV_N (3 * DD)             // 3072

// Scratch (allocation-free rule: __device__ globals) — all fp16 packed
__device__ __half g_qp[(size_t)MROWS * DD];      // 16 MB packed-A Q (x0.125)
__device__ __half g_kp[(size_t)MROWS * DD];      // 16 MB packed-B K (QK layout)
__device__ __half g_vp[(size_t)MROWS * DD];      // 16 MB packed-B V (PV layout)
__device__ __half g_att[(size_t)MROWS * DD];     // 16 MB packed-A attention out
__device__ __half g_xt[(size_t)MROWS * DD];      // 16 MB packed-A x
__device__ __half g_wqkv[(size_t)DD * QKV_N];    //  6 MB packed-B qkv_w
__device__ __half g_wproj[(size_t)DD * DD];      //  2 MB packed-B proj_w

__device__ __forceinline__ uint32_t h2u(float a, float b) {
    __half2 h = __floats2half2_rn(a, b);
    return *reinterpret_cast<uint32_t*>(&h);
}

__device__ __forceinline__ void mma_f16(float c[4], uint4 a, uint2 b) {
    asm volatile(
        "mma.sync.aligned.m16n8k16.row.col.f32.f16.f16.f32 "
        "{%0,%1,%2,%3}, {%4,%5,%6,%7}, {%8,%9}, {%0,%1,%2,%3};"
        : "+f"(c[0]), "+f"(c[1]), "+f"(c[2]), "+f"(c[3])
        : "r"(a.x), "r"(a.y), "r"(a.z), "r"(a.w), "r"(b.x), "r"(b.y));
}

__device__ __forceinline__ void cp16(void* dst, const void* src) {
    uint32_t d = (uint32_t)__cvta_generic_to_shared(dst);
    asm volatile("cp.async.cg.shared.global [%0], [%1], 16;" :: "r"(d), "l"(src));
}
__device__ __forceinline__ void cp_commit() {
    asm volatile("cp.async.commit_group;");
}
template <int N> __device__ __forceinline__ void cp_wait() {
    asm volatile("cp.async.wait_group %0;" :: "n"(N));
}

// ---------------------------------------------------------------------------
// Fused prepass (unchanged from R15).
// ---------------------------------------------------------------------------
__global__ __launch_bounds__(256) void pack_all_kernel(
    const float* __restrict__ x, const float* __restrict__ qkv_w,
    const float* __restrict__ proj_w,
    uint4* __restrict__ xt, uint2* __restrict__ wqkv, uint2* __restrict__ wproj)
{
    __shared__ float sm[16 * 260];
    const int t = threadIdx.x;
    const int bid = blockIdx.x;

    if (bid < 4096) {
        const int am  = bid >> 3;
        const int ak0 = (bid & 7) * 8;
        const int K = DD;
        const float* src = x + (size_t)am * 16 * K + ak0 * 16;
#pragma unroll
        for (int u = 0; u < 8; u++) {
            int idx = u * 256 + t;
            int r = idx >> 7, c = idx & 127;
            sm[r * 132 + c] = src[(size_t)r * K + c];
        }
        __syncthreads();
        const int j = t >> 5, lane = t & 31;
        const int gr = lane >> 2, gc = lane & 3;
        const int k0 = j * 16;
        uint4 v;
        v.x = h2u(sm[gr * 132 + k0 + 2 * gc],       sm[gr * 132 + k0 + 2 * gc + 1]);
        v.y = h2u(sm[(gr + 8) * 132 + k0 + 2 * gc], sm[(gr + 8) * 132 + k0 + 2 * gc + 1]);
        v.z = h2u(sm[gr * 132 + k0 + 2 * gc + 8],   sm[gr * 132 + k0 + 2 * gc + 9]);
        v.w = h2u(sm[(gr + 8) * 132 + k0 + 2 * gc + 8], sm[(gr + 8) * 132 + k0 + 2 * gc + 9]);
        xt[((size_t)am * (K >> 4) + ak0 + j) * 32 + lane] = v;
    } else {
        const float* in;
        uint2* outp;
        int N, id;
        if (bid < 4096 + 768) { id = bid - 4096; in = qkv_w; outp = wqkv; N = QKV_N; }
        else                  { id = bid - 4864; in = proj_w; outp = wproj; N = DD; }
        const int nb = N / 256;
        const int ak  = id / nb;
        const int an0 = (id % nb) * 32;
        const float* src = in + (size_t)ak * 16 * N + an0 * 8;
#pragma unroll
        for (int u = 0; u < 16; u++) {
            int idx = u * 256 + t;
            int r = idx >> 8, c = idx & 255;
            sm[r * 260 + c] = src[(size_t)r * N + c];
        }
        __syncthreads();
#pragma unroll
        for (int u = 0; u < 4; u++) {
            int wv = u * 256 + t;
            int an = wv >> 5, lane = wv & 31;
            int gr = lane >> 2, gc = lane & 3;
            uint2 v;
            v.x = h2u(sm[(2 * gc) * 260 + an * 8 + gr],
                      sm[(2 * gc + 1) * 260 + an * 8 + gr]);
            v.y = h2u(sm[(2 * gc + 8) * 260 + an * 8 + gr],
                      sm[(2 * gc + 9) * 260 + an * 8 + gr]);
            outp[((size_t)ak * (N >> 3) + an0 + an) * 32 + lane] = v;
        }
    }
}

// ---------------------------------------------------------------------------
// FP16 GEMM, 512 threads, warp = 64M x 16N (32 accumulators -> reg slack).
// 16 warps tile 128x128 as 2M x 8N. Same SMEM stage layout as R15.
// MODE 0: row-major fp32 C + bias (proj). MODE 2: scatter packed Q/K/V.
// ---------------------------------------------------------------------------
template <int MODE>
__global__ __launch_bounds__(512, 1) void gemm_f16_kernel(
    const __half* __restrict__ Ap, const __half* __restrict__ Bp,
    const float* __restrict__ bias, float* __restrict__ C,
    __half* __restrict__ qp, __half* __restrict__ kp, __half* __restrict__ vp,
    int M, int N, int K)
{
    extern __shared__ float smf[];
    char* smb = (char*)smf;

    const int tid  = threadIdx.x;
    const int lane = tid & 31;
    const int warp = tid >> 5;            // 0..15
    const int bm = blockIdx.y * 128;
    const int bn = blockIdx.x * 128;
    const int wm2 = (warp & 1) * 4;       // m-atom base: 0 or 4
    const int wn2 = (warp >> 1) * 2;      // n-atom base: 0..14
    const int gr = lane >> 2;
    const int gc = lane & 3;
    const int K16 = K >> 4, N8 = N >> 3;

    auto prefetch = [&](int t, int s) {
        char* Ad = smb + s * 32768;
        char* Bd = Ad + 16384;
#pragma unroll
        for (int u = 0; u < 2; u++) {
            int c = u * 512 + tid;                    // 0..1023 x 16B
            int ai = c >> 7, aj = (c >> 5) & 3, al = c & 31;
            const char* ag = (const char*)Ap
                + (((size_t)((bm >> 4) + ai) * K16 + t * 4 + aj) * 32 + al) * 16;
            cp16(Ad + c * 16, ag);
            int ks2 = c >> 8, rr = c & 255;
            const char* bg = (const char*)Bp
                + ((size_t)(t * 4 + ks2) * N8 + (bn >> 3)) * 256 + rr * 16;
            cp16(Bd + c * 16, bg);
        }
    };

    float c[4][2][4];
#pragma unroll
    for (int i = 0; i < 4; i++)
#pragma unroll
        for (int j = 0; j < 2; j++)
#pragma unroll
            for (int r = 0; r < 4; r++) c[i][j][r] = 0.0f;

    const int nit = K / 64;
    prefetch(0, 0); cp_commit();
    prefetch(1, 1); cp_commit();

    for (int t = 0; t < nit; t++) {
        if (t + 1 < nit) cp_wait<1>(); else cp_wait<0>();
        __syncthreads();
        if (t + 2 < nit) { prefetch(t + 2, (t + 2) % 3); cp_commit(); }

        const char* st = smb + (t % 3) * 32768;
        const uint4* Af = (const uint4*)st;
        const uint2* Bf = (const uint2*)(st + 16384);

#pragma unroll
        for (int ks = 0; ks < 4; ks++) {
            uint4 a4[4];
#pragma unroll
            for (int i = 0; i < 4; i++)
                a4[i] = Af[(((wm2 + i) << 2) + ks) * 32 + lane];
            uint2 b2[2];
#pragma unroll
            for (int j = 0; j < 2; j++)
                b2[j] = Bf[((ks << 4) + wn2 + j) * 32 + lane];
#pragma unroll
            for (int i = 0; i < 4; i++)
#pragma unroll
                for (int j = 0; j < 2; j++)
                    mma_f16(c[i][j], a4[i], b2[j]);
        }
    }

    if (MODE == 0) {
#pragma unroll
        for (int i = 0; i < 4; i++) {
#pragma unroll
            for (int j = 0; j < 2; j++) {
                int row = bm + (wm2 + i) * 16 + gr;
                int col = bn + (wn2 + j) * 8 + 2 * gc;
                float bx = bias[col], by = bias[col + 1];
                *(float2*)(C + (size_t)row * N + col) =
                    make_float2(c[i][j][0] + bx, c[i][j][1] + by);
                *(float2*)(C + (size_t)(row + 8) * N + col) =
                    make_float2(c[i][j][2] + bx, c[i][j][3] + by);
            }
        }
    } else {
        const int sec = bn >> 10;
#pragma unroll
        for (int i = 0; i < 4; i++) {
#pragma unroll
            for (int j = 0; j < 2; j++) {
                int row = bm + (wm2 + i) * 16 + gr;
                int col = bn + (wn2 + j) * 8 + 2 * gc;
                float v0 = c[i][j][0] + bias[col];
                float v1 = c[i][j][1] + bias[col + 1];
                float v2 = c[i][j][2] + bias[col];
                float v3 = c[i][j][3] + bias[col + 1];
                int tt = row & 2047, b_ = row >> 11;
                int h_ = (col & 1023) >> 6, d = col & 63;
                int bh = b_ * HH + h_;
                if (sec == 0) {
                    int kk = d & 15;
                    char* base = (char*)qp
                        + ((((size_t)bh * 128 + (tt >> 4)) * 4 + (d >> 4)) * 512)
                        + ((tt & 7) * 4 + ((kk & 7) >> 1)) * 16 + ((kk >= 8) ? 8 : 0);
                    uint2 st2;
                    st2.x = h2u(v0 * 0.125f, v1 * 0.125f);
                    st2.y = h2u(v2 * 0.125f, v3 * 0.125f);
                    *(uint2*)base = st2;
                } else if (sec == 1) {
                    int kk = d & 15;
                    size_t atom = ((size_t)bh * 32 + (tt >> 6)) * 32
                                + (d >> 4) * 8 + ((tt >> 3) & 7);
                    int off = ((tt & 7) * 4 + ((kk & 7) >> 1)) * 8 + ((kk >= 8) ? 4 : 0);
                    *(uint32_t*)((char*)kp + atom * 256 + off) = h2u(v0, v1);
                    size_t atom8 = atom + 1;
                    *(uint32_t*)((char*)kp + atom8 * 256 + off) = h2u(v2, v3);
                } else {
                    auto wrv = [&](float v, int ttv, int dv) {
                        size_t atom = ((size_t)bh * 32 + (ttv >> 6)) * 32
                                    + ((ttv >> 4) & 3) * 8 + (dv >> 3);
                        int off = ((dv & 7) * 4 + ((ttv & 7) >> 1)) * 8
                                + (((ttv & 15) >= 8) ? 4 : 0) + (ttv & 1) * 2;
                        *(__half*)((char*)vp + atom * 256 + off) = __float2half_rn(v);
                    };
                    wrv(v0, tt, d); wrv(v1, tt, d + 1);
                    wrv(v2, tt + 8, d); wrv(v3, tt + 8, d + 1);
                }
            }
        }
    }
}

// ---------------------------------------------------------------------------
// FP16 causal flash attention (unchanged from R15): 64-query tiles, occ 4.
// ---------------------------------------------------------------------------
__global__ __launch_bounds__(128, 4) void attn_f16_kernel(
    const __half* __restrict__ qp, const __half* __restrict__ kp,
    const __half* __restrict__ vp, __half* __restrict__ outp)
{
    extern __shared__ float smf[];
    char* Pp  = (char*)smf;
    char* Kb0 = Pp + 8192;
    char* Kb1 = Kb0 + 8192;
    char* Vb0 = Kb1 + 8192;
    char* Vb1 = Vb0 + 8192;

    const int tid  = threadIdx.x;
    const int lane = tid & 31;
    const int w    = tid >> 5;
    const int gr   = lane >> 2;
    const int gc   = lane & 3;
    const int qt = gridDim.x - 1 - blockIdx.x;
    const int h  = blockIdx.y;
    const int b  = blockIdx.z;
    const int bh = b * HH + h;
    const int qbase_g = qt * 64;

    const char* kbase = (const char*)kp + (size_t)bh * 32 * 8192;
    const char* vbase = (const char*)vp + (size_t)bh * 32 * 8192;

    auto prefetch = [&](int kt, int pb) {
        char* Kd = pb ? Kb1 : Kb0;
        char* Vd = pb ? Vb1 : Vb0;
        const char* ks_ = kbase + (size_t)kt * 8192;
        const char* vs_ = vbase + (size_t)kt * 8192;
#pragma unroll
        for (int u = 0; u < 4; u++) {
            int c = u * 128 + tid;
            cp16(Kd + c * 16, ks_ + c * 16);
            cp16(Vd + c * 16, vs_ + c * 16);
        }
    };

    prefetch(0, 0); cp_commit();

    uint4 qf[4];
    {
        const uint4* qg = (const uint4*)qp
            + ((size_t)bh * 128 + qt * 4 + w) * 4 * 32 + lane;
#pragma unroll
        for (int ks = 0; ks < 4; ks++)
            qf[ks] = qg[ks * 32];
    }

    float o[8][4];
#pragma unroll
    for (int j = 0; j < 8; j++)
#pragma unroll
        for (int r = 0; r < 4; r++) o[j][r] = 0.0f;
    float m0 = -1e30f, m1 = -1e30f, l0 = 0.0f, l1 = 0.0f;

    const int wbase_g = qbase_g + w * 16;
    const int ntiles = qt + 1;
    for (int kt = 0; kt < ntiles; kt++) {
        cp_wait<0>();
        __syncthreads();
        if (kt + 1 < ntiles) { prefetch(kt + 1, (kt + 1) & 1); cp_commit(); }
        const uint2* Kf = (const uint2*)((kt & 1) ? Kb1 : Kb0);
        const uint2* Vf = (const uint2*)((kt & 1) ? Vb1 : Vb0);

        float s[8][4];
#pragma unroll
        for (int j = 0; j < 8; j++) {
            s[j][0] = s[j][1] = s[j][2] = s[j][3] = 0.0f;
#pragma unroll
            for (int ks = 0; ks < 4; ks++)
                mma_f16(s[j], qf[ks], Kf[(ks * 8 + j) * 32 + lane]);
        }

        if (kt * 64 + 63 > wbase_g) {
            const int row0 = wbase_g + gr;
            const int row1 = row0 + 8;
#pragma unroll
            for (int j = 0; j < 8; j++) {
                int key0 = kt * 64 + j * 8 + 2 * gc;
                if (key0     > row0) s[j][0] = -1e30f;
                if (key0 + 1 > row0) s[j][1] = -1e30f;
                if (key0     > row1) s[j][2] = -1e30f;
                if (key0 + 1 > row1) s[j][3] = -1e30f;
            }
        }

        float mx0 = -1e30f, mx1 = -1e30f;
#pragma unroll
        for (int j = 0; j < 8; j++) {
            mx0 = fmaxf(mx0, fmaxf(s[j][0], s[j][1]));
            mx1 = fmaxf(mx1, fmaxf(s[j][2], s[j][3]));
        }
        mx0 = fmaxf(mx0, __shfl_xor_sync(0xffffffffu, mx0, 1));
        mx0 = fmaxf(mx0, __shfl_xor_sync(0xffffffffu, mx0, 2));
        mx1 = fmaxf(mx1, __shfl_xor_sync(0xffffffffu, mx1, 1));
        mx1 = fmaxf(mx1, __shfl_xor_sync(0xffffffffu, mx1, 2));

        float mn0 = fmaxf(m0, mx0), mn1 = fmaxf(m1, mx1);
        float cr0 = __expf(m0 - mn0), cr1 = __expf(m1 - mn1);
        l0 *= cr0; l1 *= cr1;
#pragma unroll
        for (int j = 0; j < 8; j++) {
            o[j][0] *= cr0; o[j][1] *= cr0;
            o[j][2] *= cr1; o[j][3] *= cr1;
        }

        float rs0 = 0.0f, rs1 = 0.0f;
        char* pbase = Pp + w * 2048;
        const int loff = (gr * 4 + gc) * 16;
#pragma unroll
        for (int j = 0; j < 8; j++) {
            float p0 = __expf(s[j][0] - mn0);
            float p1 = __expf(s[j][1] - mn0);
            float p2 = __expf(s[j][2] - mn1);
            float p3 = __expf(s[j][3] - mn1);
            rs0 += p0 + p1; rs1 += p2 + p3;
            uint2 st2;
            st2.x = h2u(p0, p1);
            st2.y = h2u(p2, p3);
            *(uint2*)(pbase + (j >> 1) * 512 + loff + (j & 1) * 8) = st2;
        }
        rs0 += __shfl_xor_sync(0xffffffffu, rs0, 1);
        rs0 += __shfl_xor_sync(0xffffffffu, rs0, 2);
        rs1 += __shfl_xor_sync(0xffffffffu, rs1, 1);
        rs1 += __shfl_xor_sync(0xffffffffu, rs1, 2);
        l0 += rs0; l1 += rs1;
        m0 = mn0; m1 = mn1;
        __syncwarp();

        uint4 pf[4];
#pragma unroll
        for (int kc = 0; kc < 4; kc++)
            pf[kc] = *(const uint4*)(pbase + kc * 512 + lane * 16);
#pragma unroll
        for (int jd = 0; jd < 8; jd++)
#pragma unroll
            for (int kc = 0; kc < 4; kc++)
                mma_f16(o[jd], pf[kc], Vf[(kc * 8 + jd) * 32 + lane]);
    }

    float iv0 = 1.0f / l0, iv1 = 1.0f / l1;
    int rowg = b * TT + wbase_g;
    size_t ratom = (size_t)(rowg >> 4);
#pragma unroll
    for (int jd = 0; jd < 8; jd++) {
        size_t katom = h * 4 + (jd >> 1);
        char* base = (char*)outp + (ratom * 64 + katom) * 512
                   + (gr * 4 + gc) * 16 + (jd & 1) * 8;
        uint2 st2;
        st2.x = h2u(o[jd][0] * iv0, o[jd][1] * iv0);
        st2.y = h2u(o[jd][2] * iv1, o[jd][3] * iv1);
        *(uint2*)base = st2;
    }
}

// ---------------------------------------------------------------------------
// Launch
// ---------------------------------------------------------------------------
extern "C" void kernel_launch(void* const* d_in, const int* in_sizes, int n_in,
                              void* d_out, int out_size)
{
    const float* x      = (const float*)d_in[0];
    const float* qkv_w  = (const float*)d_in[1];
    const float* qkv_b  = (const float*)d_in[2];
    const float* proj_w = (const float*)d_in[3];
    const float* proj_b = (const float*)d_in[4];
    float* out = (float*)d_out;

    __half *qp, *kpp, *vpp, *att_s, *xt, *wqkv, *wproj;
    cudaGetSymbolAddress((void**)&qp,    g_qp);
    cudaGetSymbolAddress((void**)&kpp,   g_kp);
    cudaGetSymbolAddress((void**)&vpp,   g_vp);
    cudaGetSymbolAddress((void**)&att_s, g_att);
    cudaGetSymbolAddress((void**)&xt,    g_xt);
    cudaGetSymbolAddress((void**)&wqkv,  g_wqkv);
    cudaGetSymbolAddress((void**)&wproj, g_wproj);

    const int GEMM_SMEM = 3 * 32768;     // 98304
    const int ATTN_SMEM = 40 * 1024;     // 40960
    cudaFuncSetAttribute(gemm_f16_kernel<2>,
                         cudaFuncAttributeMaxDynamicSharedMemorySize, GEMM_SMEM);
    cudaFuncSetAttribute(gemm_f16_kernel<0>,
                         cudaFuncAttributeMaxDynamicSharedMemorySize, GEMM_SMEM);
    cudaFuncSetAttribute(attn_f16_kernel,
                         cudaFuncAttributeMaxDynamicSharedMemorySize, ATTN_SMEM);

    // 0) Fused prepass
    pack_all_kernel<<<5120, 256>>>(x, qkv_w, proj_w,
                                   (uint4*)xt, (uint2*)wqkv, (uint2*)wproj);

    // 1) QKV GEMM -> packed Q / K / V (512-thread, small-warp-tile)
    dim3 g1(QKV_N / 128, MROWS / 128);
    gemm_f16_kernel<2><<<g1, 512, GEMM_SMEM>>>(xt, wqkv, qkv_b, nullptr,
                                               qp, kpp, vpp, MROWS, QKV_N, DD);

    // 2) Causal multi-head attention (unchanged)
    dim3 ga(TT / 64, HH, BB);
    attn_f16_kernel<<<ga, 128, ATTN_SMEM>>>(qp, kpp, vpp, att_s);

    // 3) Output projection
    dim3 g2(DD / 128, MROWS / 128);
    gemm_f16_kernel<0><<<g2, 512, GEMM_SMEM>>>(att_s, wproj, proj_b, out,
                                               nullptr, nullptr, nullptr,
                                               MROWS, DD, DD);
}

// round 17
// speedup vs baseline: 1.3082x; 1.3082x over previous
#include <cuda_runtime.h>
#include <cuda_fp16.h>
#include <cstdint>

// Problem constants
#define BB 4
#define TT 2048
#define DD 1024
#define HH 16
#define HDIM 64
#define MROWS (BB * TT)            // 8192
#define QKV_N (3 * DD)             // 3072

// Scratch (allocation-free rule: __device__ globals) — all fp16 packed
__device__ __half g_qp[(size_t)MROWS * DD];      // 16 MB packed-A Q (x0.125)
__device__ __half g_kp[(size_t)MROWS * DD];      // 16 MB packed-B K (QK layout)
__device__ __half g_vp[(size_t)MROWS * DD];      // 16 MB packed-B V (PV layout)
__device__ __half g_att[(size_t)MROWS * DD];     // 16 MB packed-A attention out
__device__ __half g_xt[(size_t)MROWS * DD];      // 16 MB packed-A x
__device__ __half g_wqkv[(size_t)DD * QKV_N];    //  6 MB packed-B qkv_w
__device__ __half g_wproj[(size_t)DD * DD];      //  2 MB packed-B proj_w

__device__ __forceinline__ uint32_t h2u(float a, float b) {
    __half2 h = __floats2half2_rn(a, b);
    return *reinterpret_cast<uint32_t*>(&h);
}

__device__ __forceinline__ void mma_f16(float c[4], uint4 a, uint2 b) {
    asm volatile(
        "mma.sync.aligned.m16n8k16.row.col.f32.f16.f16.f32 "
        "{%0,%1,%2,%3}, {%4,%5,%6,%7}, {%8,%9}, {%0,%1,%2,%3};"
        : "+f"(c[0]), "+f"(c[1]), "+f"(c[2]), "+f"(c[3])
        : "r"(a.x), "r"(a.y), "r"(a.z), "r"(a.w), "r"(b.x), "r"(b.y));
}

__device__ __forceinline__ void cp16(void* dst, const void* src) {
    uint32_t d = (uint32_t)__cvta_generic_to_shared(dst);
    asm volatile("cp.async.cg.shared.global [%0], [%1], 16;" :: "r"(d), "l"(src));
}
__device__ __forceinline__ void cp_commit() {
    asm volatile("cp.async.commit_group;");
}
template <int N> __device__ __forceinline__ void cp_wait() {
    asm volatile("cp.async.wait_group %0;" :: "n"(N));
}

// ---------------------------------------------------------------------------
// Fused prepass: one launch packs x (A-atoms) + qkv_w + proj_w (B-atoms).
// ---------------------------------------------------------------------------
__global__ __launch_bounds__(256) void pack_all_kernel(
    const float* __restrict__ x, const float* __restrict__ qkv_w,
    const float* __restrict__ proj_w,
    uint4* __restrict__ xt, uint2* __restrict__ wqkv, uint2* __restrict__ wproj)
{
    __shared__ float sm[16 * 260];
    const int t = threadIdx.x;
    const int bid = blockIdx.x;

    if (bid < 4096) {
        const int am  = bid >> 3;
        const int ak0 = (bid & 7) * 8;
        const int K = DD;
        const float* src = x + (size_t)am * 16 * K + ak0 * 16;
#pragma unroll
        for (int u = 0; u < 8; u++) {
            int idx = u * 256 + t;
            int r = idx >> 7, c = idx & 127;
            sm[r * 132 + c] = src[(size_t)r * K + c];
        }
        __syncthreads();
        const int j = t >> 5, lane = t & 31;
        const int gr = lane >> 2, gc = lane & 3;
        const int k0 = j * 16;
        uint4 v;
        v.x = h2u(sm[gr * 132 + k0 + 2 * gc],       sm[gr * 132 + k0 + 2 * gc + 1]);
        v.y = h2u(sm[(gr + 8) * 132 + k0 + 2 * gc], sm[(gr + 8) * 132 + k0 + 2 * gc + 1]);
        v.z = h2u(sm[gr * 132 + k0 + 2 * gc + 8],   sm[gr * 132 + k0 + 2 * gc + 9]);
        v.w = h2u(sm[(gr + 8) * 132 + k0 + 2 * gc + 8], sm[(gr + 8) * 132 + k0 + 2 * gc + 9]);
        xt[((size_t)am * (K >> 4) + ak0 + j) * 32 + lane] = v;
    } else {
        const float* in;
        uint2* outp;
        int N, id;
        if (bid < 4096 + 768) { id = bid - 4096; in = qkv_w; outp = wqkv; N = QKV_N; }
        else                  { id = bid - 4864; in = proj_w; outp = wproj; N = DD; }
        const int nb = N / 256;
        const int ak  = id / nb;
        const int an0 = (id % nb) * 32;
        const float* src = in + (size_t)ak * 16 * N + an0 * 8;
#pragma unroll
        for (int u = 0; u < 16; u++) {
            int idx = u * 256 + t;
            int r = idx >> 8, c = idx & 255;
            sm[r * 260 + c] = src[(size_t)r * N + c];
        }
        __syncthreads();
#pragma unroll
        for (int u = 0; u < 4; u++) {
            int wv = u * 256 + t;
            int an = wv >> 5, lane = wv & 31;
            int gr = lane >> 2, gc = lane & 3;
            uint2 v;
            v.x = h2u(sm[(2 * gc) * 260 + an * 8 + gr],
                      sm[(2 * gc + 1) * 260 + an * 8 + gr]);
            v.y = h2u(sm[(2 * gc + 8) * 260 + an * 8 + gr],
                      sm[(2 * gc + 9) * 260 + an * 8 + gr]);
            outp[((size_t)ak * (N >> 3) + an0 + an) * 32 + lane] = v;
        }
    }
}

// ---------------------------------------------------------------------------
// FP16 GEMM on packed operands (R13 layout; incremental prefetch addressing).
// MODE 0: row-major fp32 C + bias (proj). MODE 2: scatter packed Q/K/V.
// ---------------------------------------------------------------------------
template <int MODE>
__global__ __launch_bounds__(256, 2) void gemm_f16_kernel(
    const __half* __restrict__ Ap, const __half* __restrict__ Bp,
    const float* __restrict__ bias, float* __restrict__ C,
    __half* __restrict__ qp, __half* __restrict__ kp, __half* __restrict__ vp,
    int M, int N, int K)
{
    extern __shared__ float smf[];
    char* smb = (char*)smf;

    const int tid  = threadIdx.x;
    const int lane = tid & 31;
    const int warp = tid >> 5;
    const int bm = blockIdx.y * 128;
    const int bn = blockIdx.x * 128;
    const int wm2 = (warp & 1) * 4;
    const int wn2 = (warp >> 1) * 4;
    const int gr = lane >> 2;
    const int gc = lane & 3;
    const int K16 = K >> 4, N8 = N >> 3;

    // Incremental prefetch bases (advance by constant strides in t and u)
    const char* abase = (const char*)Ap
        + (((size_t)((bm >> 4) + (tid >> 7)) * K16 + ((tid >> 5) & 3)) * 32
           + (tid & 31)) * 16;
    const char* bbase = (const char*)Bp
        + ((size_t)((bn >> 3) + (tid >> 4))) * 256 + (tid & 15) * 16;
    const size_t a_us = (size_t)K16 * 1024;    // A stride per u
    const size_t b_us = (size_t)N8 * 256;      // B stride per u
    const size_t b_ts = (size_t)N8 * 1024;     // B stride per t

    auto prefetch = [&](int t, int s) {
        char* Ad = smb + s * 32768 + tid * 16;
        char* Bd = Ad + 16384;
        const char* ag = abase + (size_t)t * 2048;
        const char* bg = bbase + (size_t)t * b_ts;
#pragma unroll
        for (int u = 0; u < 4; u++) {
            cp16(Ad + u * 4096, ag); ag += a_us;
            cp16(Bd + u * 4096, bg); bg += b_us;
        }
    };

    float c[4][4][4];
#pragma unroll
    for (int i = 0; i < 4; i++)
#pragma unroll
        for (int j = 0; j < 4; j++)
#pragma unroll
            for (int r = 0; r < 4; r++) c[i][j][r] = 0.0f;

    const int nit = K / 64;
    prefetch(0, 0); cp_commit();
    prefetch(1, 1); cp_commit();

    for (int t = 0; t < nit; t++) {
        if (t + 1 < nit) cp_wait<1>(); else cp_wait<0>();
        __syncthreads();
        if (t + 2 < nit) { prefetch(t + 2, (t + 2) % 3); cp_commit(); }

        const char* st = smb + (t % 3) * 32768;
        const uint4* Af = (const uint4*)st;
        const uint2* Bf = (const uint2*)(st + 16384);

#pragma unroll
        for (int ks = 0; ks < 4; ks++) {
            uint4 a4[4];
#pragma unroll
            for (int i = 0; i < 4; i++)
                a4[i] = Af[(((wm2 + i) << 2) + ks) * 32 + lane];
            uint2 b2[4];
#pragma unroll
            for (int j = 0; j < 4; j++)
                b2[j] = Bf[((ks << 4) + wn2 + j) * 32 + lane];
#pragma unroll
            for (int i = 0; i < 4; i++)
#pragma unroll
                for (int j = 0; j < 4; j++)
                    mma_f16(c[i][j], a4[i], b2[j]);
        }
    }

    if (MODE == 0) {
#pragma unroll
        for (int i = 0; i < 4; i++) {
#pragma unroll
            for (int j = 0; j < 4; j++) {
                int row = bm + (wm2 + i) * 16 + gr;
                int col = bn + (wn2 + j) * 8 + 2 * gc;
                float bx = bias[col], by = bias[col + 1];
                *(float2*)(C + (size_t)row * N + col) =
                    make_float2(c[i][j][0] + bx, c[i][j][1] + by);
                *(float2*)(C + (size_t)(row + 8) * N + col) =
                    make_float2(c[i][j][2] + bx, c[i][j][3] + by);
            }
        }
    } else {
        const int sec = bn >> 10;
#pragma unroll
        for (int i = 0; i < 4; i++) {
#pragma unroll
            for (int j = 0; j < 4; j++) {
                int row = bm + (wm2 + i) * 16 + gr;
                int col = bn + (wn2 + j) * 8 + 2 * gc;
                float v0 = c[i][j][0] + bias[col];
                float v1 = c[i][j][1] + bias[col + 1];
                float v2 = c[i][j][2] + bias[col];
                float v3 = c[i][j][3] + bias[col + 1];
                int tt = row & 2047, b_ = row >> 11;
                int h_ = (col & 1023) >> 6, d = col & 63;
                int bh = b_ * HH + h_;
                if (sec == 0) {
                    int kk = d & 15;
                    char* base = (char*)qp
                        + ((((size_t)bh * 128 + (tt >> 4)) * 4 + (d >> 4)) * 512)
                        + ((tt & 7) * 4 + ((kk & 7) >> 1)) * 16 + ((kk >= 8) ? 8 : 0);
                    uint2 st2;
                    st2.x = h2u(v0 * 0.125f, v1 * 0.125f);
                    st2.y = h2u(v2 * 0.125f, v3 * 0.125f);
                    *(uint2*)base = st2;
                } else if (sec == 1) {
                    int kk = d & 15;
                    size_t atom = ((size_t)bh * 32 + (tt >> 6)) * 32
                                + (d >> 4) * 8 + ((tt >> 3) & 7);
                    int off = ((tt & 7) * 4 + ((kk & 7) >> 1)) * 8 + ((kk >= 8) ? 4 : 0);
                    *(uint32_t*)((char*)kp + atom * 256 + off) = h2u(v0, v1);
                    size_t atom8 = atom + 1;
                    *(uint32_t*)((char*)kp + atom8 * 256 + off) = h2u(v2, v3);
                } else {
                    auto wrv = [&](float v, int ttv, int dv) {
                        size_t atom = ((size_t)bh * 32 + (ttv >> 6)) * 32
                                    + ((ttv >> 4) & 3) * 8 + (dv >> 3);
                        int off = ((dv & 7) * 4 + ((ttv & 7) >> 1)) * 8
                                + (((ttv & 15) >= 8) ? 4 : 0) + (ttv & 1) * 2;
                        *(__half*)((char*)vp + atom * 256 + off) = __float2half_rn(v);
                    };
                    wrv(v0, tt, d); wrv(v1, tt, d + 1);
                    wrv(v2, tt + 8, d); wrv(v3, tt + 8, d + 1);
                }
            }
        }
    }
}

// ---------------------------------------------------------------------------
// FP16 causal flash attention, 64-query tiles, occupancy 4.
// SMEM: P 8KB + 2x(K 8KB) + 2x(V 8KB) = 40KB.
// ---------------------------------------------------------------------------
__global__ __launch_bounds__(128, 4) void attn_f16_kernel(
    const __half* __restrict__ qp, const __half* __restrict__ kp,
    const __half* __restrict__ vp, __half* __restrict__ outp)
{
    extern __shared__ float smf[];
    char* Pp  = (char*)smf;            // 8 KB (4 warps x 2KB)
    char* Kb0 = Pp + 8192;             // 8 KB each
    char* Kb1 = Kb0 + 8192;
    char* Vb0 = Kb1 + 8192;
    char* Vb1 = Vb0 + 8192;

    const int tid  = threadIdx.x;
    const int lane = tid & 31;
    const int w    = tid >> 5;
    const int gr   = lane >> 2;
    const int gc   = lane & 3;
    const int qt = gridDim.x - 1 - blockIdx.x;   // heavy blocks first
    const int h  = blockIdx.y;
    const int b  = blockIdx.z;
    const int bh = b * HH + h;
    const int qbase_g = qt * 64;

    const char* kbase = (const char*)kp + (size_t)bh * 32 * 8192;
    const char* vbase = (const char*)vp + (size_t)bh * 32 * 8192;

    auto prefetch = [&](int kt, int pb) {
        char* Kd = pb ? Kb1 : Kb0;
        char* Vd = pb ? Vb1 : Vb0;
        const char* ks_ = kbase + (size_t)kt * 8192;
        const char* vs_ = vbase + (size_t)kt * 8192;
#pragma unroll
        for (int u = 0; u < 4; u++) {
            int c = u * 128 + tid;                // 0..511 x 16B
            cp16(Kd + c * 16, ks_ + c * 16);
            cp16(Vd + c * 16, vs_ + c * 16);
        }
    };

    prefetch(0, 0); cp_commit();

    // ---- Q fragments: direct LDG.128 from packed Q (warp = 16 rows) ----
    uint4 qf[4];
    {
        const uint4* qg = (const uint4*)qp
            + ((size_t)bh * 128 + qt * 4 + w) * 4 * 32 + lane;
#pragma unroll
        for (int ks = 0; ks < 4; ks++)
            qf[ks] = qg[ks * 32];
    }

    float o[8][4];
#pragma unroll
    for (int j = 0; j < 8; j++)
#pragma unroll
        for (int r = 0; r < 4; r++) o[j][r] = 0.0f;
    float m0 = -1e30f, m1 = -1e30f, l0 = 0.0f, l1 = 0.0f;

    const int wbase_g = qbase_g + w * 16;
    const int ntiles = qt + 1;
    for (int kt = 0; kt < ntiles; kt++) {
        cp_wait<0>();
        __syncthreads();
        if (kt + 1 < ntiles) { prefetch(kt + 1, (kt + 1) & 1); cp_commit(); }
        const uint2* Kf = (const uint2*)((kt & 1) ? Kb1 : Kb0);
        const uint2* Vf = (const uint2*)((kt & 1) ? Vb1 : Vb0);

        // ---- S = Q @ K^T ----
        float s[8][4];
#pragma unroll
        for (int j = 0; j < 8; j++) {
            s[j][0] = s[j][1] = s[j][2] = s[j][3] = 0.0f;
#pragma unroll
            for (int ks = 0; ks < 4; ks++)
                mma_f16(s[j], qf[ks], Kf[(ks * 8 + j) * 32 + lane]);
        }

        // ---- causal mask (boundary tile only) ----
        if (kt * 64 + 63 > wbase_g) {
            const int row0 = wbase_g + gr;
            const int row1 = row0 + 8;
#pragma unroll
            for (int j = 0; j < 8; j++) {
                int key0 = kt * 64 + j * 8 + 2 * gc;
                if (key0     > row0) s[j][0] = -1e30f;
                if (key0 + 1 > row0) s[j][1] = -1e30f;
                if (key0     > row1) s[j][2] = -1e30f;
                if (key0 + 1 > row1) s[j][3] = -1e30f;
            }
        }

        // ---- online softmax ----
        float mx0 = -1e30f, mx1 = -1e30f;
#pragma unroll
        for (int j = 0; j < 8; j++) {
            mx0 = fmaxf(mx0, fmaxf(s[j][0], s[j][1]));
            mx1 = fmaxf(mx1, fmaxf(s[j][2], s[j][3]));
        }
        mx0 = fmaxf(mx0, __shfl_xor_sync(0xffffffffu, mx0, 1));
        mx0 = fmaxf(mx0, __shfl_xor_sync(0xffffffffu, mx0, 2));
        mx1 = fmaxf(mx1, __shfl_xor_sync(0xffffffffu, mx1, 1));
        mx1 = fmaxf(mx1, __shfl_xor_sync(0xffffffffu, mx1, 2));

        float mn0 = fmaxf(m0, mx0), mn1 = fmaxf(m1, mx1);
        float cr0 = __expf(m0 - mn0), cr1 = __expf(m1 - mn1);
        l0 *= cr0; l1 *= cr1;
#pragma unroll
        for (int j = 0; j < 8; j++) {
            o[j][0] *= cr0; o[j][1] *= cr0;
            o[j][2] *= cr1; o[j][3] *= cr1;
        }

        // ---- exp + packed-P write ----
        float rs0 = 0.0f, rs1 = 0.0f;
        char* pbase = Pp + w * 2048;
        const int loff = (gr * 4 + gc) * 16;
#pragma unroll
        for (int j = 0; j < 8; j++) {
            float p0 = __expf(s[j][0] - mn0);
            float p1 = __expf(s[j][1] - mn0);
            float p2 = __expf(s[j][2] - mn1);
            float p3 = __expf(s[j][3] - mn1);
            rs0 += p0 + p1; rs1 += p2 + p3;
            uint2 st2;
            st2.x = h2u(p0, p1);
            st2.y = h2u(p2, p3);
            *(uint2*)(pbase + (j >> 1) * 512 + loff + (j & 1) * 8) = st2;
        }
        rs0 += __shfl_xor_sync(0xffffffffu, rs0, 1);
        rs0 += __shfl_xor_sync(0xffffffffu, rs0, 2);
        rs1 += __shfl_xor_sync(0xffffffffu, rs1, 1);
        rs1 += __shfl_xor_sync(0xffffffffu, rs1, 2);
        l0 += rs0; l1 += rs1;
        m0 = mn0; m1 = mn1;
        __syncwarp();   // P atoms warp-private

        // ---- P fragments + O += P @ V ----
        uint4 pf[4];
#pragma unroll
        for (int kc = 0; kc < 4; kc++)
            pf[kc] = *(const uint4*)(pbase + kc * 512 + lane * 16);
#pragma unroll
        for (int jd = 0; jd < 8; jd++)
#pragma unroll
            for (int kc = 0; kc < 4; kc++)
                mma_f16(o[jd], pf[kc], Vf[(kc * 8 + jd) * 32 + lane]);
    }

    // ---- epilogue: normalize + write packed-A fp16 for proj ----
    float iv0 = 1.0f / l0, iv1 = 1.0f / l1;
    int rowg = b * TT + wbase_g;                 // 16-aligned
    size_t ratom = (size_t)(rowg >> 4);
#pragma unroll
    for (int jd = 0; jd < 8; jd++) {
        size_t katom = h * 4 + (jd >> 1);
        char* base = (char*)outp + (ratom * 64 + katom) * 512
                   + (gr * 4 + gc) * 16 + (jd & 1) * 8;
        uint2 st2;
        st2.x = h2u(o[jd][0] * iv0, o[jd][1] * iv0);
        st2.y = h2u(o[jd][2] * iv1, o[jd][3] * iv1);
        *(uint2*)base = st2;
    }
}

// ---------------------------------------------------------------------------
// Launch
// ---------------------------------------------------------------------------
extern "C" void kernel_launch(void* const* d_in, const int* in_sizes, int n_in,
                              void* d_out, int out_size)
{
    const float* x      = (const float*)d_in[0];
    const float* qkv_w  = (const float*)d_in[1];
    const float* qkv_b  = (const float*)d_in[2];
    const float* proj_w = (const float*)d_in[3];
    const float* proj_b = (const float*)d_in[4];
    float* out = (float*)d_out;

    __half *qp, *kpp, *vpp, *att_s, *xt, *wqkv, *wproj;
    cudaGetSymbolAddress((void**)&qp,    g_qp);
    cudaGetSymbolAddress((void**)&kpp,   g_kp);
    cudaGetSymbolAddress((void**)&vpp,   g_vp);
    cudaGetSymbolAddress((void**)&att_s, g_att);
    cudaGetSymbolAddress((void**)&xt,    g_xt);
    cudaGetSymbolAddress((void**)&wqkv,  g_wqkv);
    cudaGetSymbolAddress((void**)&wproj, g_wproj);

    const int GEMM_SMEM = 3 * 32768;     // 98304
    const int ATTN_SMEM = 40 * 1024;     // 40960
    cudaFuncSetAttribute(gemm_f16_kernel<2>,
                         cudaFuncAttributeMaxDynamicSharedMemorySize, GEMM_SMEM);
    cudaFuncSetAttribute(gemm_f16_kernel<0>,
                         cudaFuncAttributeMaxDynamicSharedMemorySize, GEMM_SMEM);
    cudaFuncSetAttribute(attn_f16_kernel,
                         cudaFuncAttributeMaxDynamicSharedMemorySize, ATTN_SMEM);

    // 0) Fused prepass: pack x + both weights in one launch
    pack_all_kernel<<<5120, 256>>>(x, qkv_w, proj_w,
                                   (uint4*)xt, (uint2*)wqkv, (uint2*)wproj);

    // 1) QKV GEMM -> packed Q / K / V directly
    dim3 g1(QKV_N / 128, MROWS / 128);
    gemm_f16_kernel<2><<<g1, 256, GEMM_SMEM>>>(xt, wqkv, qkv_b, nullptr,
                                               qp, kpp, vpp, MROWS, QKV_N, DD);

    // 2) Causal multi-head attention (64-query tiles, occ 4)
    dim3 ga(TT / 64, HH, BB);
    attn_f16_kernel<<<ga, 128, ATTN_SMEM>>>(qp, kpp, vpp, att_s);

    // 3) Output projection (packed in, row-major fp32 out)
    dim3 g2(DD / 128, MROWS / 128);
    gemm_f16_kernel<0><<<g2, 256, GEMM_SMEM>>>(att_s, wproj, proj_b, out,
                                               nullptr, nullptr, nullptr,
                                               MROWS, DD, DD);
}